// round 10
// baseline (speedup 1.0000x reference)
#include <cuda_runtime.h>

#define N_   64
#define C_   128
#define T_   2048
#define EPS_ 1e-5f

typedef unsigned long long u64;

// warps per half: 16 tchunks * 64 n * 2 warps = 2048; 8 partial lanes each.
#define PARTW  8
#define NPART  (2048 * PARTW)   // 16384

__device__ float g_ps[C_][NPART];
__device__ float g_pq[C_][NPART];
__device__ float g_scale[C_];
__device__ float g_bias [C_];

__device__ __forceinline__ u64 pack2(float lo, float hi) {
    u64 r; asm("mov.b64 %0, {%1, %2};" : "=l"(r) : "f"(lo), "f"(hi)); return r;
}
__device__ __forceinline__ void unpack2(u64 v, float& lo, float& hi) {
    asm("mov.b64 {%0, %1}, %2;" : "=f"(lo), "=f"(hi) : "l"(v));
}
__device__ __forceinline__ void fma2(u64& d, u64 a, u64 b) {
    asm("fma.rn.f32x2 %0, %1, %2, %0;" : "+l"(d) : "l"(a), "l"(b));
}
__device__ __forceinline__ void add2(u64& d, u64 a) {
    asm("add.rn.f32x2 %0, %1, %0;" : "+l"(d) : "l"(a));
}

// Channel sweep: thread owns 2 time columns (t0, t0+64) packed as f32x2.
// y[c'] = x[c', t - sh(c')], sh(c') = c'%9 - 4.  out[c] = sum_s w[c,s]*y[c-4+s].
// Ring of 9 packed y-values; ring indices / shifts are compile-time.
// Weights staged in smem duplicated {w,w} (20 floats/row: 9 pairs + pad).
template<int CLO, int WRITE, int SAFE>
__device__ __forceinline__ void sweep(
    const float* __restrict__ xn, float* __restrict__ outn,
    const float* __restrict__ sw2, const float* __restrict__ ssc,
    const float* __restrict__ sbi, int t0, int bid8, int lane)
{
    const float* xt = xn + t0;
    float* ot = outn + t0;   // only dereferenced when WRITE

    u64 y[9];
    #pragma unroll
    for (int k = 0; k < 9; ++k) y[k] = 0ull;

    #pragma unroll
    for (int jj = 0; jj < 72; ++jj) {
        const int jg = CLO - 4 + jj;           // source channel being loaded
        if (jg >= 0 && jg < C_) {              // static after unroll
            const int m    = ((jg % 9) + 9) % 9;
            const int sh   = m - 4;
            const int off  = jg * T_ - sh;     // immediate offset
            if (SAFE) {
                y[m] = pack2(xt[off], xt[off + 64]);
            } else {
                int i = t0 - sh;
                float lo = ((unsigned)i < T_) ? xt[off]      : 0.f; i += 64;
                float hi = ((unsigned)i < T_) ? xt[off + 64] : 0.f;
                y[m] = pack2(lo, hi);
            }
        } else if (jg >= C_) {
            // Top channel pad: slot would otherwise hold stale channel jg-9.
            y[jg % 9] = 0ull;
        }
        if (jj >= 8) {                          // output channel c = CLO + jj - 8
            const int r = jj - 8;               // local row [0,64)
            const int c = CLO + r;
            const ulonglong2* wp = (const ulonglong2*)(sw2 + r * 20);
            const ulonglong2 wq0 = wp[0];   // {w0,w0},{w1,w1}
            const ulonglong2 wq1 = wp[1];   // {w2,w2},{w3,w3}
            const ulonglong2 wq2 = wp[2];   // {w4,w4},{w5,w5}
            const ulonglong2 wq3 = wp[3];   // {w6,w6},{w7,w7}
            const ulonglong2 wq4 = wp[4];   // {w8,w8},{pad}
            const int sb = (((jg - 8) % 9) + 9) % 9;   // slot of y[c-4]
            u64 acc0 = 0ull, acc1 = 0ull, acc2 = 0ull;
            #define SL(s) ((sb + (s)) % 9)
            fma2(acc0, wq0.x, y[SL(0)]);
            fma2(acc1, wq0.y, y[SL(1)]);
            fma2(acc2, wq1.x, y[SL(2)]);
            fma2(acc0, wq1.y, y[SL(3)]);
            fma2(acc1, wq2.x, y[SL(4)]);
            fma2(acc2, wq2.y, y[SL(5)]);
            fma2(acc0, wq3.x, y[SL(6)]);
            fma2(acc1, wq3.y, y[SL(7)]);
            fma2(acc2, wq4.x, y[SL(8)]);
            #undef SL
            add2(acc0, acc1);
            add2(acc0, acc2);
            float a0, a1;
            unpack2(acc0, a0, a1);

            if (WRITE) {
                const float sc = ssc[r];
                const float bi = sbi[r];
                ot[c * T_     ] = fmaxf(fmaf(a0, sc, bi), 0.f);
                ot[c * T_ + 64] = fmaxf(fmaf(a1, sc, bi), 0.f);
            } else {
                float s = a0 + a1;
                float q = fmaf(a0, a0, a1 * a1);
                // 2-stage butterfly: lane l holds sum over lanes == l (mod 8)
                s += __shfl_xor_sync(0xffffffffu, s, 16);
                q += __shfl_xor_sync(0xffffffffu, q, 16);
                s += __shfl_xor_sync(0xffffffffu, s, 8);
                q += __shfl_xor_sync(0xffffffffu, q, 8);
                if (lane < PARTW) {
                    g_ps[c][bid8 + lane] = s;
                    g_pq[c][bid8 + lane] = q;
                }
            }
        }
    }
}

template<int WRITE>
__global__ void __launch_bounds__(64, 16)
conv_kernel(const float* __restrict__ x, const float* __restrict__ cw,
            float* __restrict__ out)
{
    __shared__ float sw2[64 * 20];   // duplicated weight pairs + pad
    __shared__ float ssc[64], sbi[64];

    const int tid    = threadIdx.x;    // 0..63
    const int tchunk = blockIdx.x;     // 0..15 (128 t each)
    const int n      = blockIdx.y;     // 0..63
    const int half   = blockIdx.z;     // 0..1
    const int clo    = half * 64;

    for (int i = tid; i < 64 * 9; i += 64) {
        int r = i / 9, s = i - r * 9;
        float w = cw[(clo + r) * 9 + s];
        sw2[r * 20 + 2 * s    ] = w;
        sw2[r * 20 + 2 * s + 1] = w;
    }
    sw2[tid * 20 + 18] = 0.f;
    sw2[tid * 20 + 19] = 0.f;
    if (WRITE) {
        ssc[tid] = g_scale[clo + tid];
        sbi[tid] = g_bias [clo + tid];
    }
    __syncthreads();

    const int t0   = tchunk * 128 + tid;
    const int warp = tid >> 5, lane = tid & 31;
    const int tw   = tchunk * 128 + warp * 32;
    // All loads in range iff tw-4 >= 0 and tw+31+64+4 <= T-1.
    const bool safe = (tw >= 4) && (tw + 31 + 64 + 4 <= T_ - 1);
    const int bid8 = (((n * 16 + tchunk) * 2 + warp) * PARTW);

    const float* xn   = x   + (size_t)n * C_ * T_;
    float*       outn = out + (size_t)n * C_ * T_;

    if (half == 0) {
        if (safe) sweep<0, WRITE, 1>(xn, outn, sw2, ssc, sbi, t0, bid8, lane);
        else      sweep<0, WRITE, 0>(xn, outn, sw2, ssc, sbi, t0, bid8, lane);
    } else {
        if (safe) sweep<64, WRITE, 1>(xn, outn, sw2, ssc, sbi, t0, bid8, lane);
        else      sweep<64, WRITE, 0>(xn, outn, sw2, ssc, sbi, t0, bid8, lane);
    }
}

__global__ void __launch_bounds__(256)
finalize_kernel(const float* __restrict__ gamma, const float* __restrict__ beta)
{
    __shared__ float rs[256], rq[256];
    const int c = blockIdx.x;
    const int tid = threadIdx.x;
    float s = 0.f, q = 0.f;
    #pragma unroll 8
    for (int j = tid; j < NPART; j += 256) {
        s += g_ps[c][j];
        q += g_pq[c][j];
    }
    rs[tid] = s; rq[tid] = q;
    __syncthreads();
    #pragma unroll
    for (int off = 128; off > 0; off >>= 1) {
        if (tid < off) { rs[tid] += rs[tid + off]; rq[tid] += rq[tid + off]; }
        __syncthreads();
    }
    if (tid == 0) {
        const float invNT = 1.f / (float)(N_ * T_);
        const float m   = rs[0] * invNT;
        const float v   = rq[0] * invNT - m * m;
        const float inv = rsqrtf(v + EPS_);
        const float sc  = gamma[c] * inv;
        g_scale[c] = sc;
        g_bias [c] = beta[c] - m * sc;
    }
}

extern "C" void kernel_launch(void* const* d_in, const int* in_sizes, int n_in,
                              void* d_out, int out_size)
{
    const float* x     = (const float*)d_in[0];
    const float* cw    = (const float*)d_in[1];
    const float* gamma = (const float*)d_in[2];
    const float* beta  = (const float*)d_in[3];
    float* out = (float*)d_out;

    dim3 grid(16, N_, 2);
    conv_kernel<0><<<grid, 64>>>(x, cw, nullptr);
    finalize_kernel<<<C_, 256>>>(gamma, beta);
    conv_kernel<1><<<grid, 64>>>(x, cw, out);
}

// round 11
// speedup vs baseline: 1.4903x; 1.4903x over previous
#include <cuda_runtime.h>

#define N_   64
#define C_   128
#define T_   2048
#define EPS_ 1e-5f

// Stats writers per channel: 16 tchunks * 64 n * 2 warps = 2048 warps, 8 lanes.
#define PARTW  8
#define NPART  (2048 * PARTW)   // 16384

__device__ float g_ps[C_][NPART];
__device__ float g_pq[C_][NPART];
__device__ float g_scale[C_];
__device__ float g_bias [C_];

// Channel-quarter sweep: thread owns 2 time columns (t0, t0+64).
// y[c'] = x[c', t - sh(c')], sh(c') = c'%9 - 4.  out[c] = sum_s w[c,s]*y[c-4+s].
// Ring of 9 y-values per column; ring indices / shifts compile-time.
// Writes RAW conv output (normalization applied by a later pass).
template<int CLO, int SAFE>
__device__ __forceinline__ void sweep(
    const float* __restrict__ xn, float* __restrict__ outn,
    const float* __restrict__ sw, int t0, int bid8, int lane)
{
    const float* xt = xn + t0;
    float* ot = outn + t0;

    float y0[9], y1[9];
    #pragma unroll
    for (int k = 0; k < 9; ++k) { y0[k] = 0.f; y1[k] = 0.f; }

    #pragma unroll
    for (int jj = 0; jj < 40; ++jj) {
        // ---- load source channel jg (guarded at compile time) ----
        const int jg = CLO - 4 + jj;
        if (jg >= 0 && jg < C_) {
            const int m    = ((jg % 9) + 9) % 9;
            const int sh   = m - 4;
            const int off  = jg * T_ - sh;
            if (SAFE) {
                y0[m] = xt[off];
                y1[m] = xt[off + 64];
            } else {
                int i = t0 - sh;
                y0[m] = ((unsigned)i < T_) ? xt[off]      : 0.f; i += 64;
                y1[m] = ((unsigned)i < T_) ? xt[off + 64] : 0.f;
            }
        } else if (jg >= C_) {
            const int m = jg % 9;   // clear stale slot (top channel pad)
            y0[m] = 0.f; y1[m] = 0.f;
        }
        // ---- emit output channel c = CLO + jj - 8 ----
        if (jj >= 8) {
            const int r = jj - 8;              // local row [0,32)
            const int c = CLO + r;
            const float4 wA = *(const float4*)(sw + r * 12);
            const float4 wB = *(const float4*)(sw + r * 12 + 4);
            const float  w8 = sw[r * 12 + 8];
            const int sb = (((jg - 8) % 9) + 9) % 9;   // slot of y[c-4]
            // 3-way accumulator split: chains of 3 FMAs, not 9.
            float p0 = 0.f, p1 = 0.f, p2 = 0.f;
            float q0 = 0.f, q1 = 0.f, q2 = 0.f;
            #define SL(s) ((sb + (s)) % 9)
            p0 = fmaf(wA.x, y0[SL(0)], p0); q0 = fmaf(wA.x, y1[SL(0)], q0);
            p1 = fmaf(wA.y, y0[SL(1)], p1); q1 = fmaf(wA.y, y1[SL(1)], q1);
            p2 = fmaf(wA.z, y0[SL(2)], p2); q2 = fmaf(wA.z, y1[SL(2)], q2);
            p0 = fmaf(wA.w, y0[SL(3)], p0); q0 = fmaf(wA.w, y1[SL(3)], q0);
            p1 = fmaf(wB.x, y0[SL(4)], p1); q1 = fmaf(wB.x, y1[SL(4)], q1);
            p2 = fmaf(wB.y, y0[SL(5)], p2); q2 = fmaf(wB.y, y1[SL(5)], q2);
            p0 = fmaf(wB.z, y0[SL(6)], p0); q0 = fmaf(wB.z, y1[SL(6)], q0);
            p1 = fmaf(wB.w, y0[SL(7)], p1); q1 = fmaf(wB.w, y1[SL(7)], q1);
            p2 = fmaf(w8,   y0[SL(8)], p2); q2 = fmaf(w8,   y1[SL(8)], q2);
            #undef SL
            const float a0 = (p0 + p1) + p2;
            const float a1 = (q0 + q1) + q2;

            // raw conv store (normalized later)
            ot[c * T_     ] = a0;
            ot[c * T_ + 64] = a1;

            // stats partials
            float s = a0 + a1;
            float q = fmaf(a0, a0, a1 * a1);
            s += __shfl_xor_sync(0xffffffffu, s, 16);
            q += __shfl_xor_sync(0xffffffffu, q, 16);
            s += __shfl_xor_sync(0xffffffffu, s, 8);
            q += __shfl_xor_sync(0xffffffffu, q, 8);
            if (lane < PARTW) {
                g_ps[c][bid8 + lane] = s;
                g_pq[c][bid8 + lane] = q;
            }
        }
    }
}

__global__ void __launch_bounds__(64, 24)
conv_kernel(const float* __restrict__ x, const float* __restrict__ cw,
            float* __restrict__ out)
{
    __shared__ float sw[32 * 12];

    const int tid    = threadIdx.x;    // 0..63
    const int tchunk = blockIdx.x;     // 0..15 (128 t each)
    const int n      = blockIdx.y;     // 0..63
    const int quart  = blockIdx.z;     // 0..3 (32 channels each)
    const int clo    = quart * 32;

    for (int i = tid; i < 32 * 9; i += 64) {
        int r = i / 9, s = i - r * 9;
        sw[r * 12 + s] = cw[(clo + r) * 9 + s];
    }
    __syncthreads();

    const int t0   = tchunk * 128 + tid;
    const int warp = tid >> 5, lane = tid & 31;
    const int tw   = tchunk * 128 + warp * 32;
    const bool safe = (tw >= 4) && (tw + 31 + 64 + 4 <= T_ - 1);
    const int bid8 = (((n * 16 + tchunk) * 2 + warp) * PARTW);

    const float* xn   = x   + (size_t)n * C_ * T_;
    float*       outn = out + (size_t)n * C_ * T_;

    switch (quart) {
    case 0: if (safe) sweep<0,1>(xn,outn,sw,t0,bid8,lane);  else sweep<0,0>(xn,outn,sw,t0,bid8,lane);  break;
    case 1: if (safe) sweep<32,1>(xn,outn,sw,t0,bid8,lane); else sweep<32,0>(xn,outn,sw,t0,bid8,lane); break;
    case 2: if (safe) sweep<64,1>(xn,outn,sw,t0,bid8,lane); else sweep<64,0>(xn,outn,sw,t0,bid8,lane); break;
    default:if (safe) sweep<96,1>(xn,outn,sw,t0,bid8,lane); else sweep<96,0>(xn,outn,sw,t0,bid8,lane); break;
    }
}

__global__ void __launch_bounds__(256)
finalize_kernel(const float* __restrict__ gamma, const float* __restrict__ beta)
{
    __shared__ float rs[256], rq[256];
    const int c = blockIdx.x;
    const int tid = threadIdx.x;
    float s = 0.f, q = 0.f;
    #pragma unroll 8
    for (int j = tid; j < NPART; j += 256) {
        s += g_ps[c][j];
        q += g_pq[c][j];
    }
    rs[tid] = s; rq[tid] = q;
    __syncthreads();
    #pragma unroll
    for (int off = 128; off > 0; off >>= 1) {
        if (tid < off) { rs[tid] += rs[tid + off]; rq[tid] += rq[tid + off]; }
        __syncthreads();
    }
    if (tid == 0) {
        const float invNT = 1.f / (float)(N_ * T_);
        const float m   = rs[0] * invNT;
        const float v   = rq[0] * invNT - m * m;
        const float inv = rsqrtf(v + EPS_);
        const float sc  = gamma[c] * inv;
        g_scale[c] = sc;
        g_bias [c] = beta[c] - m * sc;
    }
}

// Elementwise: out = relu(out * scale[c] + bias[c]), in-place, float4.
// T_/4 = 512 float4 per (n,c) row, so c = (idx4 >> 9) & 127.
#define NF4 (N_ * C_ * T_ / 4)   // 4194304
__global__ void __launch_bounds__(256)
normalize_kernel(float4* __restrict__ out)
{
    const int stride = gridDim.x * blockDim.x;
    for (int i = blockIdx.x * blockDim.x + threadIdx.x; i < NF4; i += stride) {
        const int c = (i >> 9) & (C_ - 1);
        const float sc = g_scale[c];
        const float bi = g_bias[c];
        float4 v = out[i];
        v.x = fmaxf(fmaf(v.x, sc, bi), 0.f);
        v.y = fmaxf(fmaf(v.y, sc, bi), 0.f);
        v.z = fmaxf(fmaf(v.z, sc, bi), 0.f);
        v.w = fmaxf(fmaf(v.w, sc, bi), 0.f);
        out[i] = v;
    }
}

extern "C" void kernel_launch(void* const* d_in, const int* in_sizes, int n_in,
                              void* d_out, int out_size)
{
    const float* x     = (const float*)d_in[0];
    const float* cw    = (const float*)d_in[1];
    const float* gamma = (const float*)d_in[2];
    const float* beta  = (const float*)d_in[3];
    float* out = (float*)d_out;

    dim3 grid(16, N_, 4);
    conv_kernel<<<grid, 64>>>(x, cw, out);
    finalize_kernel<<<C_, 256>>>(gamma, beta);
    normalize_kernel<<<4096, 256>>>((float4*)out);
}

// round 13
// speedup vs baseline: 1.4911x; 1.0005x over previous
#include <cuda_runtime.h>

#define N_   64
#define C_   128
#define T_   2048
#define EPS_ 1e-5f

// Stats writers per channel: 16 tchunks * 64 n * 2 warps = 2048 warps, 8 lanes.
#define PARTW  8
#define NPART  (2048 * PARTW)   // 16384

__device__ float g_ps[C_][NPART];
__device__ float g_pq[C_][NPART];
__device__ float g_scale[C_];
__device__ float g_bias [C_];

// Channel-quarter sweep with PREFETCH DISTANCE 2.
// Ring of 11 slots holds channels lg-10..lg; output c consumes c-4..c+4 = lg-10..lg-2,
// so the 2 freshest loads are never on the critical path (4+ LDGs in flight/thread).
// y[c'] = x[c', t - sh(c')], sh(c') = c'%9 - 4.  out[c] = sum_s w[c,s]*y[c-4+s].
// Writes RAW conv output (normalization applied by a later pass).
template<int CLO, int SAFE>
__device__ __forceinline__ void sweep(
    const float* __restrict__ xn, float* __restrict__ outn,
    const float* __restrict__ sw, int t0, int bid8, int lane)
{
    const float* xt = xn + t0;
    float* ot = outn + t0;

    float y0[11], y1[11];
    #pragma unroll
    for (int k = 0; k < 11; ++k) { y0[k] = 0.f; y1[k] = 0.f; }

    #pragma unroll
    for (int jj = 0; jj < 42; ++jj) {
        // ---- prefetch source channel lg = CLO-4+jj (2 steps ahead of use) ----
        const int lg = CLO - 4 + jj;
        if (jj <= 39) {                       // loads needed only up to CLO+35
            if (lg >= 0 && lg < C_) {
                const int m    = ((lg % 11) + 11) % 11;
                const int sh   = ((lg % 9) + 9) % 9 - 4;
                const int off  = lg * T_ - sh;
                if (SAFE) {
                    y0[m] = xt[off];
                    y1[m] = xt[off + 64];
                } else {
                    int i = t0 - sh;
                    y0[m] = ((unsigned)i < T_) ? xt[off]      : 0.f; i += 64;
                    y1[m] = ((unsigned)i < T_) ? xt[off + 64] : 0.f;
                }
            } else if (lg >= C_) {
                const int m = ((lg % 11) + 11) % 11;  // clear stale slot (top pad)
                y0[m] = 0.f; y1[m] = 0.f;
            }
        }
        // ---- emit output channel c = CLO + jj - 10 ----
        if (jj >= 10) {
            const int r = jj - 10;             // local row [0,32)
            const int c = CLO + r;
            const float4 wA = *(const float4*)(sw + r * 12);
            const float4 wB = *(const float4*)(sw + r * 12 + 4);
            const float  w8 = sw[r * 12 + 8];
            const int sb = (((c - 4) % 11) + 11) % 11;   // slot of y[c-4]
            // 3-way accumulator split: chains of 3 FMAs, not 9.
            float p0 = 0.f, p1 = 0.f, p2 = 0.f;
            float q0 = 0.f, q1 = 0.f, q2 = 0.f;
            #define SL(s) ((sb + (s)) % 11)
            p0 = fmaf(wA.x, y0[SL(0)], p0); q0 = fmaf(wA.x, y1[SL(0)], q0);
            p1 = fmaf(wA.y, y0[SL(1)], p1); q1 = fmaf(wA.y, y1[SL(1)], q1);
            p2 = fmaf(wA.z, y0[SL(2)], p2); q2 = fmaf(wA.z, y1[SL(2)], q2);
            p0 = fmaf(wA.w, y0[SL(3)], p0); q0 = fmaf(wA.w, y1[SL(3)], q0);
            p1 = fmaf(wB.x, y0[SL(4)], p1); q1 = fmaf(wB.x, y1[SL(4)], q1);
            p2 = fmaf(wB.y, y0[SL(5)], p2); q2 = fmaf(wB.y, y1[SL(5)], q2);
            p0 = fmaf(wB.z, y0[SL(6)], p0); q0 = fmaf(wB.z, y1[SL(6)], q0);
            p1 = fmaf(wB.w, y0[SL(7)], p1); q1 = fmaf(wB.w, y1[SL(7)], q1);
            p2 = fmaf(w8,   y0[SL(8)], p2); q2 = fmaf(w8,   y1[SL(8)], q2);
            #undef SL
            const float a0 = (p0 + p1) + p2;
            const float a1 = (q0 + q1) + q2;

            // raw conv store (normalized later)
            ot[c * T_     ] = a0;
            ot[c * T_ + 64] = a1;

            // stats partials
            float s = a0 + a1;
            float q = fmaf(a0, a0, a1 * a1);
            s += __shfl_xor_sync(0xffffffffu, s, 16);
            q += __shfl_xor_sync(0xffffffffu, q, 16);
            s += __shfl_xor_sync(0xffffffffu, s, 8);
            q += __shfl_xor_sync(0xffffffffu, q, 8);
            if (lane < PARTW) {
                g_ps[c][bid8 + lane] = s;
                g_pq[c][bid8 + lane] = q;
            }
        }
    }
}

__global__ void __launch_bounds__(64, 20)
conv_kernel(const float* __restrict__ x, const float* __restrict__ cw,
            float* __restrict__ out)
{
    __shared__ float sw[32 * 12];

    const int tid    = threadIdx.x;    // 0..63
    const int tchunk = blockIdx.x;     // 0..15 (128 t each)
    const int n      = blockIdx.y;     // 0..63
    const int quart  = blockIdx.z;     // 0..3 (32 channels each)
    const int clo    = quart * 32;

    for (int i = tid; i < 32 * 9; i += 64) {
        int r = i / 9, s = i - r * 9;
        sw[r * 12 + s] = cw[(clo + r) * 9 + s];
    }
    __syncthreads();

    const int t0   = tchunk * 128 + tid;
    const int warp = tid >> 5, lane = tid & 31;
    const int tw   = tchunk * 128 + warp * 32;
    const bool safe = (tw >= 4) && (tw + 31 + 64 + 4 <= T_ - 1);
    const int bid8 = (((n * 16 + tchunk) * 2 + warp) * PARTW);

    const float* xn   = x   + (size_t)n * C_ * T_;
    float*       outn = out + (size_t)n * C_ * T_;

    switch (quart) {
    case 0: if (safe) sweep<0,1>(xn,outn,sw,t0,bid8,lane);  else sweep<0,0>(xn,outn,sw,t0,bid8,lane);  break;
    case 1: if (safe) sweep<32,1>(xn,outn,sw,t0,bid8,lane); else sweep<32,0>(xn,outn,sw,t0,bid8,lane); break;
    case 2: if (safe) sweep<64,1>(xn,outn,sw,t0,bid8,lane); else sweep<64,0>(xn,outn,sw,t0,bid8,lane); break;
    default:if (safe) sweep<96,1>(xn,outn,sw,t0,bid8,lane); else sweep<96,0>(xn,outn,sw,t0,bid8,lane); break;
    }
}

__global__ void __launch_bounds__(256)
finalize_kernel(const float* __restrict__ gamma, const float* __restrict__ beta)
{
    __shared__ float rs[256], rq[256];
    const int c = blockIdx.x;
    const int tid = threadIdx.x;
    float s = 0.f, q = 0.f;
    #pragma unroll 8
    for (int j = tid; j < NPART; j += 256) {
        s += g_ps[c][j];
        q += g_pq[c][j];
    }
    rs[tid] = s; rq[tid] = q;
    __syncthreads();
    #pragma unroll
    for (int off = 128; off > 0; off >>= 1) {
        if (tid < off) { rs[tid] += rs[tid + off]; rq[tid] += rq[tid + off]; }
        __syncthreads();
    }
    if (tid == 0) {
        const float invNT = 1.f / (float)(N_ * T_);
        const float m   = rs[0] * invNT;
        const float v   = rq[0] * invNT - m * m;
        const float inv = rsqrtf(v + EPS_);
        const float sc  = gamma[c] * inv;
        g_scale[c] = sc;
        g_bias [c] = beta[c] - m * sc;
    }
}

// Elementwise: out = relu(out * scale[c] + bias[c]), in-place, float4.
// T_/4 = 512 float4 per (n,c) row, so c = (idx4 >> 9) & 127.
#define NF4 (N_ * C_ * T_ / 4)   // 4194304
__global__ void __launch_bounds__(256)
normalize_kernel(float4* __restrict__ out)
{
    const int stride = gridDim.x * blockDim.x;
    for (int i = blockIdx.x * blockDim.x + threadIdx.x; i < NF4; i += stride) {
        const int c = (i >> 9) & (C_ - 1);
        const float sc = g_scale[c];
        const float bi = g_bias[c];
        float4 v = out[i];
        v.x = fmaxf(fmaf(v.x, sc, bi), 0.f);
        v.y = fmaxf(fmaf(v.y, sc, bi), 0.f);
        v.z = fmaxf(fmaf(v.z, sc, bi), 0.f);
        v.w = fmaxf(fmaf(v.w, sc, bi), 0.f);
        out[i] = v;
    }
}

extern "C" void kernel_launch(void* const* d_in, const int* in_sizes, int n_in,
                              void* d_out, int out_size)
{
    const float* x     = (const float*)d_in[0];
    const float* cw    = (const float*)d_in[1];
    const float* gamma = (const float*)d_in[2];
    const float* beta  = (const float*)d_in[3];
    float* out = (float*)d_out;

    dim3 grid(16, N_, 4);
    conv_kernel<<<grid, 64>>>(x, cw, out);
    finalize_kernel<<<C_, 256>>>(gamma, beta);
    normalize_kernel<<<4096, 256>>>((float4*)out);
}

// round 14
// speedup vs baseline: 1.5448x; 1.0360x over previous
#include <cuda_runtime.h>

#define N_   64
#define C_   128
#define T_   2048
#define EPS_ 1e-5f

// Stats writers per channel: 16 tchunks * 64 n * 2 warps = 2048 warps, 8 lanes.
#define PARTW  8
#define NPART  (2048 * PARTW)   // 16384

__device__ float2 g_psq[C_][NPART];   // {sum, sumsq} packed

// Batch-4 pipelined channel sweep. Ring of 16 slots (mod-16 free).
// Iteration k: load channels CLO-4+4k .. CLO-1+4k (8 back-to-back LDGs),
// then (k>=3) compute outputs CLO+4(k-3) .. CLO+3+4(k-3) — newest needed
// channel was loaded at k-1, so compute never waits on a fresh LDG.
// y[c'] = x[c', t - sh(c')], sh(c') = c'%9 - 4.  out[c] = sum_s w[c,s]*y[c-4+s].
// Writes RAW conv output (normalization applied by the fused pass).
template<int CLO, int SAFE>
__device__ __forceinline__ void sweep(
    const float* __restrict__ xn, float* __restrict__ outn,
    const float* __restrict__ sw, int t0, int bid8, int lane)
{
    const float* xt = xn + t0;
    float* ot = outn + t0;

    float y0[16], y1[16];
    #pragma unroll
    for (int k = 0; k < 16; ++k) { y0[k] = 0.f; y1[k] = 0.f; }

    #pragma unroll
    for (int k = 0; k < 11; ++k) {
        // ---- load group k: 4 channels, 8 independent LDGs ----
        if (k <= 9) {
            #pragma unroll
            for (int u = 0; u < 4; ++u) {
                const int lg = CLO - 4 + 4 * k + u;      // source channel
                const int m  = ((4 * k + u - 4) % 16 + 16) % 16;  // CLO%16==0
                if (lg >= 0 && lg < C_) {
                    const int sh  = ((lg % 9) + 9) % 9 - 4;
                    const int off = lg * T_ - sh;
                    if (SAFE) {
                        y0[m] = xt[off];
                        y1[m] = xt[off + 64];
                    } else {
                        int i = t0 - sh;
                        y0[m] = ((unsigned)i < T_) ? xt[off]      : 0.f; i += 64;
                        y1[m] = ((unsigned)i < T_) ? xt[off + 64] : 0.f;
                    }
                } else if (lg >= C_) {
                    y0[m] = 0.f; y1[m] = 0.f;   // top channel pad
                }
            }
        }
        // ---- compute group k-3: 4 outputs ----
        if (k >= 3) {
            #pragma unroll
            for (int u = 0; u < 4; ++u) {
                const int r = 4 * (k - 3) + u;          // local row [0,32)
                const int c = CLO + r;
                const float4 wA = *(const float4*)(sw + r * 12);
                const float4 wB = *(const float4*)(sw + r * 12 + 4);
                const float  w8 = sw[r * 12 + 8];
                // slot of y[c-4]: (c-4) mod 16, CLO%16==0 -> (r-4) mod 16
                const int sb = ((r - 4) % 16 + 16) % 16;
                float p0 = 0.f, p1 = 0.f, p2 = 0.f;
                float q0 = 0.f, q1 = 0.f, q2 = 0.f;
                #define SL(s) ((sb + (s)) & 15)
                p0 = fmaf(wA.x, y0[SL(0)], p0); q0 = fmaf(wA.x, y1[SL(0)], q0);
                p1 = fmaf(wA.y, y0[SL(1)], p1); q1 = fmaf(wA.y, y1[SL(1)], q1);
                p2 = fmaf(wA.z, y0[SL(2)], p2); q2 = fmaf(wA.z, y1[SL(2)], q2);
                p0 = fmaf(wA.w, y0[SL(3)], p0); q0 = fmaf(wA.w, y1[SL(3)], q0);
                p1 = fmaf(wB.x, y0[SL(4)], p1); q1 = fmaf(wB.x, y1[SL(4)], q1);
                p2 = fmaf(wB.y, y0[SL(5)], p2); q2 = fmaf(wB.y, y1[SL(5)], q2);
                p0 = fmaf(wB.z, y0[SL(6)], p0); q0 = fmaf(wB.z, y1[SL(6)], q0);
                p1 = fmaf(wB.w, y0[SL(7)], p1); q1 = fmaf(wB.w, y1[SL(7)], q1);
                p2 = fmaf(w8,   y0[SL(8)], p2); q2 = fmaf(w8,   y1[SL(8)], q2);
                #undef SL
                const float a0 = (p0 + p1) + p2;
                const float a1 = (q0 + q1) + q2;

                // raw conv store (normalized later)
                ot[c * T_     ] = a0;
                ot[c * T_ + 64] = a1;

                // stats partials: 2-stage butterfly, packed float2 store
                float s = a0 + a1;
                float q = fmaf(a0, a0, a1 * a1);
                s += __shfl_xor_sync(0xffffffffu, s, 16);
                q += __shfl_xor_sync(0xffffffffu, q, 16);
                s += __shfl_xor_sync(0xffffffffu, s, 8);
                q += __shfl_xor_sync(0xffffffffu, q, 8);
                if (lane < PARTW)
                    g_psq[c][bid8 + lane] = make_float2(s, q);
            }
        }
    }
}

__global__ void __launch_bounds__(64, 16)
conv_kernel(const float* __restrict__ x, const float* __restrict__ cw,
            float* __restrict__ out)
{
    __shared__ float sw[32 * 12];

    const int tid    = threadIdx.x;    // 0..63
    const int tchunk = blockIdx.x;     // 0..15 (128 t each)
    const int n      = blockIdx.y;     // 0..63
    const int quart  = blockIdx.z;     // 0..3 (32 channels each)
    const int clo    = quart * 32;

    for (int i = tid; i < 32 * 9; i += 64) {
        int r = i / 9, s = i - r * 9;
        sw[r * 12 + s] = cw[(clo + r) * 9 + s];
    }
    __syncthreads();

    const int t0   = tchunk * 128 + tid;
    const int warp = tid >> 5, lane = tid & 31;
    const int tw   = tchunk * 128 + warp * 32;
    const bool safe = (tw >= 4) && (tw + 31 + 64 + 4 <= T_ - 1);
    const int bid8 = (((n * 16 + tchunk) * 2 + warp) * PARTW);

    const float* xn   = x   + (size_t)n * C_ * T_;
    float*       outn = out + (size_t)n * C_ * T_;

    switch (quart) {
    case 0: if (safe) sweep<0,1>(xn,outn,sw,t0,bid8,lane);  else sweep<0,0>(xn,outn,sw,t0,bid8,lane);  break;
    case 1: if (safe) sweep<32,1>(xn,outn,sw,t0,bid8,lane); else sweep<32,0>(xn,outn,sw,t0,bid8,lane); break;
    case 2: if (safe) sweep<64,1>(xn,outn,sw,t0,bid8,lane); else sweep<64,0>(xn,outn,sw,t0,bid8,lane); break;
    default:if (safe) sweep<96,1>(xn,outn,sw,t0,bid8,lane); else sweep<96,0>(xn,outn,sw,t0,bid8,lane); break;
    }
}

// Fused finalize + normalize: block = one channel.
// Phase 1: reduce the channel's 16384 float2 partials -> scale/bias.
// Phase 2: stream-normalize the channel's 64 x 2048 elements in-place (float4).
__global__ void __launch_bounds__(512)
finalize_normalize_kernel(const float* __restrict__ gamma,
                          const float* __restrict__ beta,
                          float4* __restrict__ out)
{
    __shared__ float rs[512], rq[512];
    __shared__ float s_sc, s_bi;
    const int c   = blockIdx.x;
    const int tid = threadIdx.x;

    float s = 0.f, q = 0.f;
    #pragma unroll 8
    for (int j = tid; j < NPART; j += 512) {
        const float2 v = g_psq[c][j];
        s += v.x;
        q += v.y;
    }
    rs[tid] = s; rq[tid] = q;
    __syncthreads();
    #pragma unroll
    for (int off = 256; off > 0; off >>= 1) {
        if (tid < off) { rs[tid] += rs[tid + off]; rq[tid] += rq[tid + off]; }
        __syncthreads();
    }
    if (tid == 0) {
        const float invNT = 1.f / (float)(N_ * T_);
        const float m   = rs[0] * invNT;
        const float v   = rq[0] * invNT - m * m;
        const float inv = rsqrtf(v + EPS_);
        const float sc  = gamma[c] * inv;
        s_sc = sc;
        s_bi = beta[c] - m * sc;
    }
    __syncthreads();
    const float sc = s_sc;
    const float bi = s_bi;

    // 64 rows of 512 float4 each; thread handles one float4 per row.
    const int TF4 = T_ / 4;   // 512
    #pragma unroll 4
    for (int n = 0; n < N_; ++n) {
        const int idx = (n * C_ + c) * TF4 + tid;
        float4 v = out[idx];
        v.x = fmaxf(fmaf(v.x, sc, bi), 0.f);
        v.y = fmaxf(fmaf(v.y, sc, bi), 0.f);
        v.z = fmaxf(fmaf(v.z, sc, bi), 0.f);
        v.w = fmaxf(fmaf(v.w, sc, bi), 0.f);
        out[idx] = v;
    }
}

extern "C" void kernel_launch(void* const* d_in, const int* in_sizes, int n_in,
                              void* d_out, int out_size)
{
    const float* x     = (const float*)d_in[0];
    const float* cw    = (const float*)d_in[1];
    const float* gamma = (const float*)d_in[2];
    const float* beta  = (const float*)d_in[3];
    float* out = (float*)d_out;

    dim3 grid(16, N_, 4);
    conv_kernel<<<grid, 64>>>(x, cw, out);
    finalize_normalize_kernel<<<C_, 512>>>(gamma, beta, (float4*)out);
}